// round 15
// baseline (speedup 1.0000x reference)
#include <cuda_runtime.h>
#include <cuda_fp16.h>
#include <mma.h>
#include <cstdint>

using namespace nvcuda;
typedef __half h16;

#define HID  1024
#define G4   4096
#define BAT  64
#define TT   100
#define INS  171
#define KX   192
#define NB   128
#define SMSA 72
#define NCOND 50

// ---------------- persistent device buffers ----------------
// weight slots: 0..2 = Whh layer0..2, 3 = Wx layer1 (wih2), 4 = Wx layer2 (wih3)
__device__ h16   g_w[5][G4 * HID];
__device__ h16   g_wf[G4 * HID];          // fused W' = Wih1 x Dec (fp16)
__device__ float g_wf32[G4 * HID];
__device__ h16   g_wx0[G4 * KX];
__device__ h16   g_wx0h[G4 * KX];
__device__ h16   g_wx0l[G4 * KX];
__device__ h16   g_dec[192 * HID];
__device__ h16   g_decT[HID * KX];
__device__ float g_bias[3][G4];
__device__ float g_wxdb[G4];              // Wih1 x dec_b
__device__ float g_dbias[192];
__device__ h16   g_fr_h[TT * BAT * KX];
__device__ h16   g_fr_l[TT * BAT * KX];
__device__ h16   g_hst[3][BAT * HID];
__device__ h16   g_h2all[TT * BAT * HID];
__device__ float g_gate[3][BAT * G4];     // recurrent partials (layers 1,2)
__device__ float g_gx[NCOND][BAT * G4];
__device__ float g_pp[BAT * G4];          // pair partials (phase A W' / phase B,C K-halves)
__device__ unsigned g_pf[64 * 32];        // pair flags, one line each
__device__ unsigned g_arr[NB];
__device__ unsigned g_rel;

__device__ __forceinline__ void split2h(float v, h16& hi, h16& lo) {
    hi = __float2half(v);
    lo = __float2half(v - __half2float(hi));
}
__device__ __forceinline__ void cp16(void* dst, const void* src) {
    unsigned d = (unsigned)__cvta_generic_to_shared(dst);
    asm volatile("cp.async.cg.shared.global [%0], [%1], 16;" :: "r"(d), "l"(src));
}
#define CP_COMMIT() asm volatile("cp.async.commit_group;")
#define CP_WAITG1() asm volatile("cp.async.wait_group 1;")

// ---------------- grid barrier ----------------
__device__ __forceinline__ void gbar(unsigned gen) {
    __syncthreads();
    if (threadIdx.x == 0) {
        __threadfence();
        *(volatile unsigned*)&g_arr[blockIdx.x] = gen;
    }
    if (blockIdx.x == 0) {
        if (threadIdx.x < NB) {
            while (*(volatile unsigned*)&g_arr[threadIdx.x] < gen) { }
        }
        __syncthreads();
        if (threadIdx.x == 0) {
            __threadfence();
            *(volatile unsigned*)&g_rel = gen;
        }
    } else if (threadIdx.x == 0) {
        while (*(volatile unsigned*)&g_rel < gen) { }
        __threadfence();
    }
    __syncthreads();
}

// ---------------- prep kernels ----------------
__global__ void prep_wh(const float* __restrict__ src, int slot) {
    h16* d = g_w[slot];
    int n = G4 * HID;
    for (int i = blockIdx.x * blockDim.x + threadIdx.x; i < n; i += gridDim.x * blockDim.x) {
        int col = i >> 10, k = i & 1023;
        int j = col >> 2, g = col & 3;
        d[i] = __float2half(src[(g * HID + j) * HID + k]);
    }
}
__global__ void prep_wx0(const float* __restrict__ src) {
    int n = G4 * KX;
    for (int i = blockIdx.x * blockDim.x + threadIdx.x; i < n; i += gridDim.x * blockDim.x) {
        int col = i / KX, k = i - col * KX;
        int j = col >> 2, g = col & 3;
        float v = (k < INS) ? src[(g * HID + j) * INS + k] : 0.0f;
        g_wx0[i] = __float2half(v);
        split2h(v, g_wx0h[i], g_wx0l[i]);
    }
}
__global__ void prep_dec(const float* __restrict__ src) {
    int n = 192 * HID;
    for (int i = blockIdx.x * blockDim.x + threadIdx.x; i < n; i += gridDim.x * blockDim.x) {
        int r = i >> 10, k = i & 1023;
        float v = (r < INS) ? src[r * HID + k] : 0.0f;
        g_dec[i] = __float2half(v);
    }
    int n2 = HID * KX;
    for (int i = blockIdx.x * blockDim.x + threadIdx.x; i < n2; i += gridDim.x * blockDim.x) {
        int k = i / KX, o = i - k * KX;
        float v = (o < INS) ? src[o * HID + k] : 0.0f;
        g_decT[i] = __float2half(v);
    }
}
__global__ void prep_bias(const float* __restrict__ bi, const float* __restrict__ bh, int layer) {
    for (int i = blockIdx.x * blockDim.x + threadIdx.x; i < G4; i += gridDim.x * blockDim.x) {
        int j = i >> 2, g = i & 3;
        g_bias[layer][i] = bi[g * HID + j] + bh[g * HID + j];
    }
}
__global__ void prep_wxdb(const float* __restrict__ wih1, const float* __restrict__ db) {
    for (int i = blockIdx.x * blockDim.x + threadIdx.x; i < G4; i += gridDim.x * blockDim.x) {
        int j = i >> 2, g = i & 3;
        const float* row = wih1 + (g * HID + j) * INS;
        float s = 0.0f;
        for (int r = 0; r < INS; r++) s += row[r] * db[r];
        g_wxdb[i] = s;
    }
}
__global__ void prep_dbias(const float* __restrict__ db) {
    for (int i = blockIdx.x * blockDim.x + threadIdx.x; i < 192; i += gridDim.x * blockDim.x)
        g_dbias[i] = (i < INS) ? db[i] : 0.0f;
}
__global__ void prep_frames(const float* __restrict__ rs) {
    int n = TT * BAT * KX;
    for (int i = blockIdx.x * blockDim.x + threadIdx.x; i < n; i += gridDim.x * blockDim.x) {
        int t   = i / (BAT * KX);
        int rem = i - t * (BAT * KX);
        int b = rem / KX, k = rem - b * KX;
        float v = (k < INS) ? rs[(b * TT + t) * INS + k] : 0.0f;
        split2h(v, g_fr_h[i], g_fr_l[i]);
    }
}
__global__ void prep_zero() {
    int gid = blockIdx.x * blockDim.x + threadIdx.x;
    int stride = gridDim.x * blockDim.x;
    h16 z = __float2half(0.0f);
    for (int i = gid; i < 3 * BAT * HID; i += stride) ((h16*)g_hst)[i] = z;
    for (int i = gid; i < 3 * BAT * G4; i += stride) ((float*)g_gate)[i] = 0.0f;
    for (int i = gid; i < 64 * 32; i += stride) g_pf[i] = 0;
    for (int i = gid; i < NB; i += stride) g_arr[i] = 0;
    if (gid == 0) g_rel = 0;
}
__global__ void prep_wfcvt() {
    int n = G4 * HID;
    for (int i = blockIdx.x * blockDim.x + threadIdx.x; i < n; i += gridDim.x * blockDim.x)
        g_wf[i] = __float2half(g_wf32[i]);
}

// ---------------- pipelined single-fp16 GEMM core (accumulates into acc) ----------------
template <int NF>
__device__ __forceinline__ void run_gemm(
    wmma::fragment<wmma::accumulator, 16, 16, 16, float> (&acc)[NF],
    h16* sA, h16* sB,
    int tid, int wm, int wn,
    const h16* __restrict__ a, int lda,
    const h16* __restrict__ bw, int ldb, int bcol0, int nch)
{
    wmma::fragment<wmma::accumulator, 16, 16, 16, float> accB[NF];
    #pragma unroll
    for (int nf = 0; nf < NF; nf++) wmma::fill_fragment(accB[nf], 0.0f);

    auto issue = [&](int c, int stg) {
        int k0 = c * 64;
        h16* dA = sA + stg * 64 * SMSA;
        #pragma unroll
        for (int u = 0; u < 2; u++) {
            int i = tid + u * 256;
            int r = i >> 3, s = (i & 7) * 8;
            cp16(dA + r * SMSA + s, a + r * lda + k0 + s);
        }
        h16* dB = sB + stg * (NF * 32) * SMSA;
        #pragma unroll
        for (int u = 0; u < NF; u++) {
            int i = tid + u * 256;
            int r = i >> 3, s = (i & 7) * 8;
            cp16(dB + r * SMSA + s, bw + (long)(bcol0 + r) * ldb + k0 + s);
        }
    };

    wmma::fragment<wmma::matrix_a, 16, 16, 16, h16, wmma::row_major> Af;
    wmma::fragment<wmma::matrix_b, 16, 16, 16, h16, wmma::col_major> Bf;

    issue(0, 0); CP_COMMIT();
    issue(1, 1); CP_COMMIT();

    for (int c = 0; c < nch; c++) {
        CP_WAITG1();
        __syncthreads();
        int stg = c % 3;
        if (c + 2 < nch) issue(c + 2, (c + 2) % 3);
        CP_COMMIT();
        const h16* pA = sA + stg * 64 * SMSA + wm * 16 * SMSA;
        const h16* pB = sB + stg * (NF * 32) * SMSA + wn * (NF * 16) * SMSA;
        #pragma unroll
        for (int kk = 0; kk < 4; kk++) {
            wmma::load_matrix_sync(Af, pA + kk * 16, SMSA);
            #pragma unroll
            for (int nf = 0; nf < NF; nf++) {
                wmma::load_matrix_sync(Bf, pB + nf * 16 * SMSA + kk * 16, SMSA);
                if (kk & 1) wmma::mma_sync(accB[nf], Af, Bf, accB[nf]);
                else        wmma::mma_sync(acc[nf],  Af, Bf, acc[nf]);
            }
        }
    }
    #pragma unroll
    for (int nf = 0; nf < NF; nf++)
        #pragma unroll
        for (int i = 0; i < acc[nf].num_elements; i++) acc[nf].x[i] += accB[nf].x[i];
}

// ---------------- wmma split-A 2-product GEMM (prep only) ----------------
template <int NF>
__device__ __forceinline__ void run_gemm_w(
    wmma::fragment<wmma::accumulator, 16, 16, 16, float> (&accH)[NF],
    h16* sAh, h16* sAl, h16* sB,
    int tid, int wm, int wn,
    const h16* __restrict__ ah, const h16* __restrict__ al, int lda,
    const h16* __restrict__ bw, int ldb, int bcol0, int nch)
{
    wmma::fragment<wmma::accumulator, 16, 16, 16, float> accL[NF];
    #pragma unroll
    for (int nf = 0; nf < NF; nf++) {
        wmma::fill_fragment(accH[nf], 0.0f);
        wmma::fill_fragment(accL[nf], 0.0f);
    }
    auto issue = [&](int c, int stg) {
        int k0 = c * 64;
        h16* dAh = sAh + stg * 64 * SMSA;
        h16* dAl = sAl + stg * 64 * SMSA;
        #pragma unroll
        for (int u = 0; u < 2; u++) {
            int i = tid + u * 256;
            int r = i >> 3, s = (i & 7) * 8;
            cp16(dAh + r * SMSA + s, ah + r * lda + k0 + s);
            cp16(dAl + r * SMSA + s, al + r * lda + k0 + s);
        }
        h16* dB = sB + stg * (NF * 32) * SMSA;
        #pragma unroll
        for (int u = 0; u < NF; u++) {
            int i = tid + u * 256;
            int r = i >> 3, s = (i & 7) * 8;
            cp16(dB + r * SMSA + s, bw + (long)(bcol0 + r) * ldb + k0 + s);
        }
    };
    wmma::fragment<wmma::matrix_a, 16, 16, 16, h16, wmma::row_major> Ah, Al;
    wmma::fragment<wmma::matrix_b, 16, 16, 16, h16, wmma::col_major> Bf;
    issue(0, 0); CP_COMMIT();
    issue(1, 1); CP_COMMIT();
    for (int c = 0; c < nch; c++) {
        CP_WAITG1();
        __syncthreads();
        int stg = c % 3;
        if (c + 2 < nch) issue(c + 2, (c + 2) % 3);
        CP_COMMIT();
        const h16* pAh = sAh + stg * 64 * SMSA + wm * 16 * SMSA;
        const h16* pAl = sAl + stg * 64 * SMSA + wm * 16 * SMSA;
        const h16* pB  = sB  + stg * (NF * 32) * SMSA + wn * (NF * 16) * SMSA;
        #pragma unroll
        for (int kk = 0; kk < 4; kk++) {
            wmma::load_matrix_sync(Ah, pAh + kk * 16, SMSA);
            wmma::load_matrix_sync(Al, pAl + kk * 16, SMSA);
            #pragma unroll
            for (int nf = 0; nf < NF; nf++) {
                wmma::load_matrix_sync(Bf, pB + nf * 16 * SMSA + kk * 16, SMSA);
                wmma::mma_sync(accH[nf], Ah, Bf, accH[nf]);
                wmma::mma_sync(accL[nf], Al, Bf, accL[nf]);
            }
        }
    }
    #pragma unroll
    for (int nf = 0; nf < NF; nf++)
        #pragma unroll
        for (int i = 0; i < accH[nf].num_elements; i++) accH[nf].x[i] += accL[nf].x[i];
}

#define PREP_SMEM (2 * (3 * 64 * SMSA * 2) + 3 * 128 * SMSA * 2)

__global__ __launch_bounds__(256) void prep_gx() {
    extern __shared__ char sraw[];
    h16* sAh = (h16*)sraw;
    h16* sAl = sAh + 3 * 64 * SMSA;
    h16* sB  = sAl + 3 * 64 * SMSA;
    int tid = threadIdx.x, warp = tid >> 5, wm = warp & 3, wn = warp >> 2;
    int ci = blockIdx.y;
    int t  = (ci / 5) * 10 + (ci % 5);
    int n0 = blockIdx.x * 128;
    wmma::fragment<wmma::accumulator, 16, 16, 16, float> aH[4];
    run_gemm_w<4>(aH, sAh, sAl, sB, tid, wm, wn,
                  g_fr_h + t * BAT * KX, g_fr_l + t * BAT * KX, KX,
                  g_wx0, KX, n0, 3);
    #pragma unroll
    for (int nf = 0; nf < 4; nf++)
        wmma::store_matrix_sync(&g_gx[ci][(wm * 16) * G4 + n0 + wn * 64 + nf * 16],
                                aH[nf], G4, wmma::mem_row_major);
}

__global__ __launch_bounds__(256) void prep_wf() {
    extern __shared__ char sraw[];
    h16* sAh = (h16*)sraw;
    h16* sAl = sAh + 3 * 64 * SMSA;
    h16* sB  = sAl + 3 * 64 * SMSA;
    int tid = threadIdx.x, warp = tid >> 5, wm = warp & 3, wn = warp >> 2;
    int m0 = blockIdx.x * 64;
    int n0 = blockIdx.y * 128;
    wmma::fragment<wmma::accumulator, 16, 16, 16, float> aH[4];
    run_gemm_w<4>(aH, sAh, sAl, sB, tid, wm, wn,
                  g_wx0h + (long)m0 * KX, g_wx0l + (long)m0 * KX, KX,
                  g_decT, KX, n0, 3);
    #pragma unroll
    for (int nf = 0; nf < 4; nf++)
        wmma::store_matrix_sync(&g_wf32[(long)(m0 + wm * 16) * HID + n0 + wn * 64 + nf * 16],
                                aH[nf], HID, wmma::mem_row_major);
}

// ---------------- smem layout for persist / dec_final ----------------
// sA 3*64*72*2 + sB 3*128*72*2 + cs[64][128] + cst[64][64]
#define SMEM_BYTES (3*64*SMSA*2 + 3*128*SMSA*2 + 64*128*4 + 64*64*4)

// ---------------- persistent kernel: 3 uniform phases/step ----------------
__global__ __launch_bounds__(256) void persist() {
    extern __shared__ char sraw[];
    h16* sA = (h16*)sraw;
    h16* sB = sA + 3 * 64 * SMSA;
    float* cs   = (float*)((char*)(sB + 3 * 128 * SMSA));   // [64][128]
    float* cst0 = cs + 64 * 128;                            // [64][32] (blocks 0..31)
    float* cst1 = cst0 + 64 * 32;                           // [64][16] (even blocks)
    float* cst2 = cst1 + 64 * 16;                           // [64][16] (even blocks)

    const int tid  = threadIdx.x;
    const int blk  = blockIdx.x;
    const int warp = tid >> 5;
    const int wm   = warp & 3;
    const int wn   = warp >> 2;

    for (int i = tid; i < 64 * 64; i += 256) cst0[i] = 0.0f;
    __syncthreads();

    unsigned gen = 0, pgen = 0;
    wmma::fragment<wmma::accumulator, 16, 16, 16, float> a4[4];
    wmma::fragment<wmma::accumulator, 16, 16, 16, float> a2[2];

    for (int t = 0; t < TT; t++) {
        bool cond = (t % 10) < 5;

        // ======== Phase A: 4 groups x 32 blocks, each N=128 K=1024 ========
        if (!cond) ++pgen;
        if (blk < 32) {
            // Whh0 + cell0 (32 hidden units per block)
            int n0 = blk * 128;
            #pragma unroll
            for (int nf = 0; nf < 4; nf++) wmma::fill_fragment(a4[nf], 0.0f);
            run_gemm<4>(a4, sA, sB, tid, wm, wn, g_hst[0], HID, g_w[0], HID, n0, 16);
            #pragma unroll
            for (int nf = 0; nf < 4; nf++)
                wmma::store_matrix_sync(&cs[(wm * 16) * 128 + wn * 64 + nf * 16],
                                        a4[nf], 128, wmma::mem_row_major);
            if (!cond) {
                if (tid == 0) {
                    while (*(volatile unsigned*)&g_pf[blk * 32] < pgen) { }
                    __threadfence();
                }
            }
            __syncthreads();
            const float* bias = g_bias[0];
            const float* gx = cond ? g_gx[(t / 10) * 5 + (t % 10)] : nullptr;
            for (int p = tid; p < 2048; p += 256) {
                int b = p >> 5, ul = p & 31;
                float q[4];
                #pragma unroll
                for (int m = 0; m < 4; m++) {
                    int cl = 4 * ul + m;
                    float v = cs[b * 128 + cl] + bias[n0 + cl];
                    if (gx) v += gx[b * G4 + n0 + cl];
                    else    v += g_wxdb[n0 + cl] + g_pp[b * G4 + n0 + cl];
                    q[m] = v;
                }
                float gi = 1.0f / (1.0f + expf(-q[0]));
                float gf = 1.0f / (1.0f + expf(-q[1]));
                float gg = tanhf(q[2]);
                float go = 1.0f / (1.0f + expf(-q[3]));
                float cv = gf * cst0[b * 32 + ul] + gi * gg;
                cst0[b * 32 + ul] = cv;
                float hv = go * tanhf(cv);
                g_hst[0][b * HID + blk * 32 + ul] = __float2half(hv);
            }
        } else if (blk < 64) {
            // W' x h2(t-1) partial (only needed on !cond steps)
            if (!cond) {
                int n0 = (blk - 32) * 128;
                #pragma unroll
                for (int nf = 0; nf < 4; nf++) wmma::fill_fragment(a4[nf], 0.0f);
                run_gemm<4>(a4, sA, sB, tid, wm, wn, g_hst[2], HID, g_wf, HID, n0, 16);
                #pragma unroll
                for (int nf = 0; nf < 4; nf++)
                    wmma::store_matrix_sync(&g_pp[(wm * 16) * G4 + n0 + wn * 64 + nf * 16],
                                            a4[nf], G4, wmma::mem_row_major);
                __syncthreads();
                if (tid == 0) {
                    __threadfence();
                    *(volatile unsigned*)&g_pf[(blk - 32) * 32] = pgen;
                }
            }
        } else {
            // Whh1 / Whh2 recurrent partials
            int lyr = 1 + ((blk - 64) >> 5);
            int n0  = ((blk - 64) & 31) * 128;
            #pragma unroll
            for (int nf = 0; nf < 4; nf++) wmma::fill_fragment(a4[nf], 0.0f);
            run_gemm<4>(a4, sA, sB, tid, wm, wn, g_hst[lyr], HID, g_w[lyr], HID, n0, 16);
            #pragma unroll
            for (int nf = 0; nf < 4; nf++)
                wmma::store_matrix_sync(&g_gate[lyr][(wm * 16) * G4 + n0 + wn * 64 + nf * 16],
                                        a4[nf], G4, wmma::mem_row_major);
        }
        gbar(++gen);

        // ======== Phase B: gates1 = Wih2 x h0 (K-split pairs) -> cell1 ========
        ++pgen;
        {
            int pair = blk >> 1, half = blk & 1, col0 = pair * 64, ko = half * 512;
            #pragma unroll
            for (int nf = 0; nf < 2; nf++) wmma::fill_fragment(a2[nf], 0.0f);
            run_gemm<2>(a2, sA, sB, tid, wm, wn,
                        g_hst[0] + ko, HID, g_w[3] + ko, HID, col0, 8);
            if (half) {
                float* pp = g_pp + pair * 4096;
                #pragma unroll
                for (int nf = 0; nf < 2; nf++)
                    wmma::store_matrix_sync(&pp[(wm * 16) * 64 + wn * 32 + nf * 16],
                                            a2[nf], 64, wmma::mem_row_major);
                __syncthreads();
                if (tid == 0) {
                    __threadfence();
                    *(volatile unsigned*)&g_pf[pair * 32] = pgen;
                }
            } else {
                #pragma unroll
                for (int nf = 0; nf < 2; nf++)
                    wmma::store_matrix_sync(&cs[(wm * 16) * 64 + wn * 32 + nf * 16],
                                            a2[nf], 64, wmma::mem_row_major);
                if (tid == 0) {
                    while (*(volatile unsigned*)&g_pf[pair * 32] < pgen) { }
                    __threadfence();
                }
                __syncthreads();
                const float* pp = g_pp + pair * 4096;
                const float* bias = g_bias[1];
                for (int p = tid; p < 1024; p += 256) {
                    int b = p >> 4, u = p & 15;
                    float q[4];
                    #pragma unroll
                    for (int m = 0; m < 4; m++) {
                        int cl = 4 * u + m;
                        q[m] = cs[b * 64 + cl] + pp[b * 64 + cl]
                             + g_gate[1][b * G4 + col0 + cl] + bias[col0 + cl];
                    }
                    float gi = 1.0f / (1.0f + expf(-q[0]));
                    float gf = 1.0f / (1.0f + expf(-q[1]));
                    float gg = tanhf(q[2]);
                    float go = 1.0f / (1.0f + expf(-q[3]));
                    float cv = gf * cst1[b * 16 + u] + gi * gg;
                    cst1[b * 16 + u] = cv;
                    float hv = go * tanhf(cv);
                    g_hst[1][b * HID + pair * 16 + u] = __float2half(hv);
                }
            }
        }
        gbar(++gen);

        // ======== Phase C: gates2 = Wih3 x h1 (K-split pairs) -> cell2, save h2 ========
        ++pgen;
        {
            int pair = blk >> 1, half = blk & 1, col0 = pair * 64, ko = half * 512;
            #pragma unroll
            for (int nf = 0; nf < 2; nf++) wmma::fill_fragment(a2[nf], 0.0f);
            run_gemm<2>(a2, sA, sB, tid, wm, wn,
                        g_hst[1] + ko, HID, g_w[4] + ko, HID, col0, 8);
            if (half) {
                float* pp = g_pp + pair * 4096;
                #pragma unroll
                for (int nf = 0; nf < 2; nf++)
                    wmma::store_matrix_sync(&pp[(wm * 16) * 64 + wn * 32 + nf * 16],
                                            a2[nf], 64, wmma::mem_row_major);
                __syncthreads();
                if (tid == 0) {
                    __threadfence();
                    *(volatile unsigned*)&g_pf[pair * 32] = pgen;
                }
            } else {
                #pragma unroll
                for (int nf = 0; nf < 2; nf++)
                    wmma::store_matrix_sync(&cs[(wm * 16) * 64 + wn * 32 + nf * 16],
                                            a2[nf], 64, wmma::mem_row_major);
                if (tid == 0) {
                    while (*(volatile unsigned*)&g_pf[pair * 32] < pgen) { }
                    __threadfence();
                }
                __syncthreads();
                const float* pp = g_pp + pair * 4096;
                const float* bias = g_bias[2];
                for (int p = tid; p < 1024; p += 256) {
                    int b = p >> 4, u = p & 15;
                    float q[4];
                    #pragma unroll
                    for (int m = 0; m < 4; m++) {
                        int cl = 4 * u + m;
                        q[m] = cs[b * 64 + cl] + pp[b * 64 + cl]
                             + g_gate[2][b * G4 + col0 + cl] + bias[col0 + cl];
                    }
                    float gi = 1.0f / (1.0f + expf(-q[0]));
                    float gf = 1.0f / (1.0f + expf(-q[1]));
                    float gg = tanhf(q[2]);
                    float go = 1.0f / (1.0f + expf(-q[3]));
                    float cv = gf * cst2[b * 16 + u] + gi * gg;
                    cst2[b * 16 + u] = cv;
                    float hv = go * tanhf(cv);
                    h16 hh = __float2half(hv);
                    int j = pair * 16 + u;
                    g_hst[2][b * HID + j] = hh;
                    g_h2all[(long)t * BAT * HID + b * HID + j] = hh;
                }
            }
        }
        gbar(++gen);
    }
}

// ---------------- final decoder ----------------
__global__ __launch_bounds__(256) void dec_final(float* __restrict__ out) {
    extern __shared__ char sraw[];
    h16* sA = (h16*)sraw;
    h16* sB = sA + 3 * 64 * SMSA;
    float* cs = (float*)((char*)(sB + 3 * 128 * SMSA));   // [64][96]

    int tid = threadIdx.x, warp = tid >> 5, wm = warp & 3, wn = warp >> 2;
    int t  = blockIdx.x;
    int n0 = blockIdx.y * 96;

    wmma::fragment<wmma::accumulator, 16, 16, 16, float> a3[3];
    #pragma unroll
    for (int nf = 0; nf < 3; nf++) wmma::fill_fragment(a3[nf], 0.0f);
    run_gemm<3>(a3, sA, sB, tid, wm, wn,
                g_h2all + (long)t * BAT * HID, HID, g_dec, HID, n0, 16);
    #pragma unroll
    for (int nf = 0; nf < 3; nf++)
        wmma::store_matrix_sync(&cs[(wm * 16) * 96 + wn * 48 + nf * 16],
                                a3[nf], 96, wmma::mem_row_major);
    __syncthreads();
    for (int p = tid; p < 64 * 96; p += 256) {
        int b = p / 96, u = p % 96;
        int col = n0 + u;
        if (col < INS)
            out[b * (TT * INS) + t * INS + col] = cs[b * 96 + u] + g_dbias[col];
    }
}

// ---------------- launch ----------------
extern "C" void kernel_launch(void* const* d_in, const int* in_sizes, int n_in,
                              void* d_out, int out_size) {
    const float* rs    = (const float*)d_in[0];
    const float* wih1  = (const float*)d_in[1];
    const float* whh1  = (const float*)d_in[2];
    const float* bih1  = (const float*)d_in[3];
    const float* bhh1  = (const float*)d_in[4];
    const float* wih2  = (const float*)d_in[5];
    const float* whh2  = (const float*)d_in[6];
    const float* bih2  = (const float*)d_in[7];
    const float* bhh2  = (const float*)d_in[8];
    const float* wih3  = (const float*)d_in[9];
    const float* whh3  = (const float*)d_in[10];
    const float* bih3  = (const float*)d_in[11];
    const float* bhh3  = (const float*)d_in[12];
    const float* decw  = (const float*)d_in[13];
    const float* decb  = (const float*)d_in[14];
    float* out = (float*)d_out;

    cudaFuncSetAttribute(persist,   cudaFuncAttributeMaxDynamicSharedMemorySize, SMEM_BYTES);
    cudaFuncSetAttribute(dec_final, cudaFuncAttributeMaxDynamicSharedMemorySize, SMEM_BYTES);
    cudaFuncSetAttribute(prep_gx,   cudaFuncAttributeMaxDynamicSharedMemorySize, PREP_SMEM);
    cudaFuncSetAttribute(prep_wf,   cudaFuncAttributeMaxDynamicSharedMemorySize, PREP_SMEM);

    prep_wh<<<2048, 256>>>(whh1, 0);
    prep_wh<<<2048, 256>>>(whh2, 1);
    prep_wh<<<2048, 256>>>(whh3, 2);
    prep_wh<<<2048, 256>>>(wih2, 3);
    prep_wh<<<2048, 256>>>(wih3, 4);
    prep_wx0<<<512, 256>>>(wih1);
    prep_dec<<<256, 256>>>(decw);
    prep_bias<<<16, 256>>>(bih1, bhh1, 0);
    prep_bias<<<16, 256>>>(bih2, bhh2, 1);
    prep_bias<<<16, 256>>>(bih3, bhh3, 2);
    prep_wxdb<<<16, 256>>>(wih1, decb);
    prep_dbias<<<1, 256>>>(decb);
    prep_frames<<<1024, 256>>>(rs);
    prep_zero<<<512, 256>>>();

    dim3 wfg(64, 8);
    prep_wf<<<wfg, 256, PREP_SMEM>>>();
    prep_wfcvt<<<1024, 256>>>();
    dim3 gxg(32, NCOND);
    prep_gx<<<gxg, 256, PREP_SMEM>>>();

    persist<<<NB, 256, SMEM_BYTES>>>();
    dim3 dg(TT, 2);
    dec_final<<<dg, 256, SMEM_BYTES>>>(out);
}

// round 16
// speedup vs baseline: 1.2548x; 1.2548x over previous
#include <cuda_runtime.h>
#include <cuda_fp16.h>
#include <mma.h>
#include <cstdint>

using namespace nvcuda;
typedef __half h16;

#define HID  1024
#define G4   4096
#define BAT  64
#define TT   100
#define INS  171
#define KX   192
#define NB   128
#define SMSA 72    // prep split-A core stride (chunk 64)
#define SMK  136   // main fp16 core stride (chunk 128): 68 words == 4 mod 32, conflict-free
#define NCOND 50

// ---------------- persistent device buffers ----------------
// weight slots: 0..2 = Whh layer0..2, 3 = Wx layer1 (wih2), 4 = Wx layer2 (wih3)
__device__ h16   g_w[5][G4 * HID];
__device__ h16   g_wf[G4 * HID];          // fused W' = Wih1 x Dec (fp16)
__device__ float g_wf32[G4 * HID];
__device__ h16   g_wx0[G4 * KX];
__device__ h16   g_wx0h[G4 * KX];
__device__ h16   g_wx0l[G4 * KX];
__device__ h16   g_dec[192 * HID];
__device__ h16   g_decT[HID * KX];
__device__ float g_bias[3][G4];
__device__ float g_wxdb[G4];              // Wih1 x dec_b
__device__ float g_dbias[192];
__device__ h16   g_fr_h[TT * BAT * KX];
__device__ h16   g_fr_l[TT * BAT * KX];
__device__ h16   g_hst[3][BAT * HID];
__device__ h16   g_h2all[TT * BAT * HID];
__device__ float g_gate[3][BAT * G4];     // recurrent partials (layers 1,2)
__device__ float g_gx[NCOND][BAT * G4];
__device__ unsigned g_arr[NB];
__device__ unsigned g_rel;

__device__ __forceinline__ void split2h(float v, h16& hi, h16& lo) {
    hi = __float2half(v);
    lo = __float2half(v - __half2float(hi));
}
__device__ __forceinline__ void cp16(void* dst, const void* src) {
    unsigned d = (unsigned)__cvta_generic_to_shared(dst);
    asm volatile("cp.async.cg.shared.global [%0], [%1], 16;" :: "r"(d), "l"(src));
}
#define CP_COMMIT() asm volatile("cp.async.commit_group;")
#define CP_WAITG1() asm volatile("cp.async.wait_group 1;")

// ---------------- grid barrier ----------------
__device__ __forceinline__ void gbar(unsigned gen) {
    __syncthreads();
    if (threadIdx.x == 0) {
        __threadfence();
        *(volatile unsigned*)&g_arr[blockIdx.x] = gen;
    }
    if (blockIdx.x == 0) {
        if (threadIdx.x < NB) {
            while (*(volatile unsigned*)&g_arr[threadIdx.x] < gen) { }
        }
        __syncthreads();
        if (threadIdx.x == 0) {
            __threadfence();
            *(volatile unsigned*)&g_rel = gen;
        }
    } else if (threadIdx.x == 0) {
        while (*(volatile unsigned*)&g_rel < gen) { }
        __threadfence();
    }
    __syncthreads();
}

// ---------------- prep kernels ----------------
__global__ void prep_wh(const float* __restrict__ src, int slot) {
    h16* d = g_w[slot];
    int n = G4 * HID;
    for (int i = blockIdx.x * blockDim.x + threadIdx.x; i < n; i += gridDim.x * blockDim.x) {
        int col = i >> 10, k = i & 1023;
        int j = col >> 2, g = col & 3;
        d[i] = __float2half(src[(g * HID + j) * HID + k]);
    }
}
__global__ void prep_wx0(const float* __restrict__ src) {
    int n = G4 * KX;
    for (int i = blockIdx.x * blockDim.x + threadIdx.x; i < n; i += gridDim.x * blockDim.x) {
        int col = i / KX, k = i - col * KX;
        int j = col >> 2, g = col & 3;
        float v = (k < INS) ? src[(g * HID + j) * INS + k] : 0.0f;
        g_wx0[i] = __float2half(v);
        split2h(v, g_wx0h[i], g_wx0l[i]);
    }
}
__global__ void prep_dec(const float* __restrict__ src) {
    int n = 192 * HID;
    for (int i = blockIdx.x * blockDim.x + threadIdx.x; i < n; i += gridDim.x * blockDim.x) {
        int r = i >> 10, k = i & 1023;
        float v = (r < INS) ? src[r * HID + k] : 0.0f;
        g_dec[i] = __float2half(v);
    }
    int n2 = HID * KX;
    for (int i = blockIdx.x * blockDim.x + threadIdx.x; i < n2; i += gridDim.x * blockDim.x) {
        int k = i / KX, o = i - k * KX;
        float v = (o < INS) ? src[o * HID + k] : 0.0f;
        g_decT[i] = __float2half(v);
    }
}
__global__ void prep_bias(const float* __restrict__ bi, const float* __restrict__ bh, int layer) {
    for (int i = blockIdx.x * blockDim.x + threadIdx.x; i < G4; i += gridDim.x * blockDim.x) {
        int j = i >> 2, g = i & 3;
        g_bias[layer][i] = bi[g * HID + j] + bh[g * HID + j];
    }
}
__global__ void prep_wxdb(const float* __restrict__ wih1, const float* __restrict__ db) {
    for (int i = blockIdx.x * blockDim.x + threadIdx.x; i < G4; i += gridDim.x * blockDim.x) {
        int j = i >> 2, g = i & 3;
        const float* row = wih1 + (g * HID + j) * INS;
        float s = 0.0f;
        for (int r = 0; r < INS; r++) s += row[r] * db[r];
        g_wxdb[i] = s;
    }
}
__global__ void prep_dbias(const float* __restrict__ db) {
    for (int i = blockIdx.x * blockDim.x + threadIdx.x; i < 192; i += gridDim.x * blockDim.x)
        g_dbias[i] = (i < INS) ? db[i] : 0.0f;
}
__global__ void prep_frames(const float* __restrict__ rs) {
    int n = TT * BAT * KX;
    for (int i = blockIdx.x * blockDim.x + threadIdx.x; i < n; i += gridDim.x * blockDim.x) {
        int t   = i / (BAT * KX);
        int rem = i - t * (BAT * KX);
        int b = rem / KX, k = rem - b * KX;
        float v = (k < INS) ? rs[(b * TT + t) * INS + k] : 0.0f;
        split2h(v, g_fr_h[i], g_fr_l[i]);
    }
}
__global__ void prep_zero() {
    int gid = blockIdx.x * blockDim.x + threadIdx.x;
    int stride = gridDim.x * blockDim.x;
    h16 z = __float2half(0.0f);
    for (int i = gid; i < 3 * BAT * HID; i += stride) ((h16*)g_hst)[i] = z;
    for (int i = gid; i < 3 * BAT * G4; i += stride) ((float*)g_gate)[i] = 0.0f;
    for (int i = gid; i < NB; i += stride) g_arr[i] = 0;
    if (gid == 0) g_rel = 0;
}
__global__ void prep_wfcvt() {
    int n = G4 * HID;
    for (int i = blockIdx.x * blockDim.x + threadIdx.x; i < n; i += gridDim.x * blockDim.x)
        g_wf[i] = __float2half(g_wf32[i]);
}

// ---------------- pipelined single-fp16 GEMM core, K-chunk = 128 ----------------
// A [64 x K] fp16 (lda), W [cols x K] fp16 (ldb). Block tile 64 x (NF*32).
// 8 warps: 4 m-warps x 2 n-warps. 3-stage cp.async pipeline, nch = K/128 chunks.
// Dual accumulators (kk parity) preserve ILP; merged at the end. ACCUMULATES into acc.
template <int NF>
__device__ __forceinline__ void run_gemm(
    wmma::fragment<wmma::accumulator, 16, 16, 16, float> (&acc)[NF],
    h16* sA, h16* sB,
    int tid, int wm, int wn,
    const h16* __restrict__ a, int lda,
    const h16* __restrict__ bw, int ldb, int bcol0, int nch)
{
    wmma::fragment<wmma::accumulator, 16, 16, 16, float> accB[NF];
    #pragma unroll
    for (int nf = 0; nf < NF; nf++) wmma::fill_fragment(accB[nf], 0.0f);

    auto issue = [&](int c, int stg) {
        int k0 = c * 128;
        h16* dA = sA + stg * 64 * SMK;
        #pragma unroll
        for (int u = 0; u < 4; u++) {
            int i = tid + u * 256;
            int r = i >> 4, s = (i & 15) * 8;
            cp16(dA + r * SMK + s, a + r * lda + k0 + s);
        }
        h16* dB = sB + stg * (NF * 32) * SMK;
        #pragma unroll
        for (int u = 0; u < NF * 2; u++) {
            int i = tid + u * 256;
            int r = i >> 4, s = (i & 15) * 8;
            cp16(dB + r * SMK + s, bw + (long)(bcol0 + r) * ldb + k0 + s);
        }
    };

    wmma::fragment<wmma::matrix_a, 16, 16, 16, h16, wmma::row_major> Af;
    wmma::fragment<wmma::matrix_b, 16, 16, 16, h16, wmma::col_major> Bf;

    issue(0, 0); CP_COMMIT();
    if (nch > 1) { issue(1, 1); CP_COMMIT(); }
    else { CP_COMMIT(); }

    for (int c = 0; c < nch; c++) {
        CP_WAITG1();
        __syncthreads();
        int stg = c % 3;
        if (c + 2 < nch) issue(c + 2, (c + 2) % 3);
        CP_COMMIT();
        const h16* pA = sA + stg * 64 * SMK + wm * 16 * SMK;
        const h16* pB = sB + stg * (NF * 32) * SMK + wn * (NF * 16) * SMK;
        #pragma unroll
        for (int kk = 0; kk < 8; kk++) {
            wmma::load_matrix_sync(Af, pA + kk * 16, SMK);
            #pragma unroll
            for (int nf = 0; nf < NF; nf++) {
                wmma::load_matrix_sync(Bf, pB + nf * 16 * SMK + kk * 16, SMK);
                if (kk & 1) wmma::mma_sync(accB[nf], Af, Bf, accB[nf]);
                else        wmma::mma_sync(acc[nf],  Af, Bf, acc[nf]);
            }
        }
    }
    #pragma unroll
    for (int nf = 0; nf < NF; nf++)
        #pragma unroll
        for (int i = 0; i < acc[nf].num_elements; i++) acc[nf].x[i] += accB[nf].x[i];
}

// ---------------- wmma split-A 2-product GEMM (prep only, K-chunk 64) ----------------
template <int NF>
__device__ __forceinline__ void run_gemm_w(
    wmma::fragment<wmma::accumulator, 16, 16, 16, float> (&accH)[NF],
    h16* sAh, h16* sAl, h16* sB,
    int tid, int wm, int wn,
    const h16* __restrict__ ah, const h16* __restrict__ al, int lda,
    const h16* __restrict__ bw, int ldb, int bcol0, int nch)
{
    wmma::fragment<wmma::accumulator, 16, 16, 16, float> accL[NF];
    #pragma unroll
    for (int nf = 0; nf < NF; nf++) {
        wmma::fill_fragment(accH[nf], 0.0f);
        wmma::fill_fragment(accL[nf], 0.0f);
    }
    auto issue = [&](int c, int stg) {
        int k0 = c * 64;
        h16* dAh = sAh + stg * 64 * SMSA;
        h16* dAl = sAl + stg * 64 * SMSA;
        #pragma unroll
        for (int u = 0; u < 2; u++) {
            int i = tid + u * 256;
            int r = i >> 3, s = (i & 7) * 8;
            cp16(dAh + r * SMSA + s, ah + r * lda + k0 + s);
            cp16(dAl + r * SMSA + s, al + r * lda + k0 + s);
        }
        h16* dB = sB + stg * (NF * 32) * SMSA;
        #pragma unroll
        for (int u = 0; u < NF; u++) {
            int i = tid + u * 256;
            int r = i >> 3, s = (i & 7) * 8;
            cp16(dB + r * SMSA + s, bw + (long)(bcol0 + r) * ldb + k0 + s);
        }
    };
    wmma::fragment<wmma::matrix_a, 16, 16, 16, h16, wmma::row_major> Ah, Al;
    wmma::fragment<wmma::matrix_b, 16, 16, 16, h16, wmma::col_major> Bf;
    issue(0, 0); CP_COMMIT();
    issue(1, 1); CP_COMMIT();
    for (int c = 0; c < nch; c++) {
        CP_WAITG1();
        __syncthreads();
        int stg = c % 3;
        if (c + 2 < nch) issue(c + 2, (c + 2) % 3);
        CP_COMMIT();
        const h16* pAh = sAh + stg * 64 * SMSA + wm * 16 * SMSA;
        const h16* pAl = sAl + stg * 64 * SMSA + wm * 16 * SMSA;
        const h16* pB  = sB  + stg * (NF * 32) * SMSA + wn * (NF * 16) * SMSA;
        #pragma unroll
        for (int kk = 0; kk < 4; kk++) {
            wmma::load_matrix_sync(Ah, pAh + kk * 16, SMSA);
            wmma::load_matrix_sync(Al, pAl + kk * 16, SMSA);
            #pragma unroll
            for (int nf = 0; nf < NF; nf++) {
                wmma::load_matrix_sync(Bf, pB + nf * 16 * SMSA + kk * 16, SMSA);
                wmma::mma_sync(accH[nf], Ah, Bf, accH[nf]);
                wmma::mma_sync(accL[nf], Al, Bf, accL[nf]);
            }
        }
    }
    #pragma unroll
    for (int nf = 0; nf < NF; nf++)
        #pragma unroll
        for (int i = 0; i < accH[nf].num_elements; i++) accH[nf].x[i] += accL[nf].x[i];
}

#define PREP_SMEM (2 * (3 * 64 * SMSA * 2) + 3 * 128 * SMSA * 2)

__global__ __launch_bounds__(256) void prep_gx() {
    extern __shared__ char sraw[];
    h16* sAh = (h16*)sraw;
    h16* sAl = sAh + 3 * 64 * SMSA;
    h16* sB  = sAl + 3 * 64 * SMSA;
    int tid = threadIdx.x, warp = tid >> 5, wm = warp & 3, wn = warp >> 2;
    int ci = blockIdx.y;
    int t  = (ci / 5) * 10 + (ci % 5);
    int n0 = blockIdx.x * 128;
    wmma::fragment<wmma::accumulator, 16, 16, 16, float> aH[4];
    run_gemm_w<4>(aH, sAh, sAl, sB, tid, wm, wn,
                  g_fr_h + t * BAT * KX, g_fr_l + t * BAT * KX, KX,
                  g_wx0, KX, n0, 3);
    #pragma unroll
    for (int nf = 0; nf < 4; nf++)
        wmma::store_matrix_sync(&g_gx[ci][(wm * 16) * G4 + n0 + wn * 64 + nf * 16],
                                aH[nf], G4, wmma::mem_row_major);
}

__global__ __launch_bounds__(256) void prep_wf() {
    extern __shared__ char sraw[];
    h16* sAh = (h16*)sraw;
    h16* sAl = sAh + 3 * 64 * SMSA;
    h16* sB  = sAl + 3 * 64 * SMSA;
    int tid = threadIdx.x, warp = tid >> 5, wm = warp & 3, wn = warp >> 2;
    int m0 = blockIdx.x * 64;
    int n0 = blockIdx.y * 128;
    wmma::fragment<wmma::accumulator, 16, 16, 16, float> aH[4];
    run_gemm_w<4>(aH, sAh, sAl, sB, tid, wm, wn,
                  g_wx0h + (long)m0 * KX, g_wx0l + (long)m0 * KX, KX,
                  g_decT, KX, n0, 3);
    #pragma unroll
    for (int nf = 0; nf < 4; nf++)
        wmma::store_matrix_sync(&g_wf32[(long)(m0 + wm * 16) * HID + n0 + wn * 64 + nf * 16],
                                aH[nf], HID, wmma::mem_row_major);
}

// ---------------- smem layout for persist / dec_final (chunk-128 core) ----------------
// sA 3*64*136*2 = 52224 ; sB 3*128*136*2 = 104448 ; cs [64][96] 24576 ; cst [64][32] 8192
#define SMEM_BYTES (3*64*SMK*2 + 3*128*SMK*2 + 64*96*4 + 64*32*4)

// ---------------- persistent kernel: whole T loop (3 barriers/step) ----------------
__global__ __launch_bounds__(256) void persist() {
    extern __shared__ char sraw[];
    h16* sA = (h16*)sraw;                            // [3][64][SMK]
    h16* sB = sA + 3 * 64 * SMK;                     // [3][128][SMK]
    float* cs  = (float*)((char*)(sB + 3 * 128 * SMK));   // [64][96] region
    float* cst = cs + 64 * 96;

    const int tid  = threadIdx.x;
    const int blk  = blockIdx.x;
    const int warp = tid >> 5;
    const int wm   = warp & 3;
    const int wn   = warp >> 2;

    for (int i = tid; i < 64 * 32; i += 256) cst[i] = 0.0f;
    __syncthreads();

    float* cst1  = cst;              // [64][8]  phase B
    float* cst2  = cst + 64 * 8;     // [64][8]  phase C
    float* cst0r = cst + 64 * 16;    // [64][16] layer0 (blk < 64)

    unsigned gen = 0;
    wmma::fragment<wmma::accumulator, 16, 16, 16, float> a2[2];
    wmma::fragment<wmma::accumulator, 16, 16, 16, float> a1[1];
    wmma::fragment<wmma::accumulator, 16, 16, 16, float> a4[4];

    for (int t = 0; t < TT; t++) {
        bool cond = (t % 10) < 5;

        // ---- Phase A ----
        if (blk < 64) {
            // layer0: N=64 tile (16 units), K = 1024 (+1024 fused on !cond)
            int n0 = blk * 64;
            #pragma unroll
            for (int nf = 0; nf < 2; nf++) wmma::fill_fragment(a2[nf], 0.0f);
            run_gemm<2>(a2, sA, sB, tid, wm, wn, g_hst[0], HID, g_w[0], HID, n0, 8);
            if (!cond)
                run_gemm<2>(a2, sA, sB, tid, wm, wn, g_hst[2], HID, g_wf, HID, n0, 8);
            #pragma unroll
            for (int nf = 0; nf < 2; nf++)
                wmma::store_matrix_sync(&cs[(wm * 16) * 64 + wn * 32 + nf * 16],
                                        a2[nf], 64, wmma::mem_row_major);
            __syncthreads();
            // cell0 for 16 units
            const float* bias = g_bias[0];
            const float* gx = cond ? g_gx[(t / 10) * 5 + (t % 10)] : nullptr;
            for (int p = tid; p < 1024; p += 256) {
                int b = p >> 4, u = p & 15;
                float q[4];
                #pragma unroll
                for (int m = 0; m < 4; m++) {
                    int cl = 4 * u + m;
                    float v = cs[b * 64 + cl] + bias[n0 + cl];
                    v += gx ? gx[b * G4 + n0 + cl] : g_wxdb[n0 + cl];
                    q[m] = v;
                }
                float gi = 1.0f / (1.0f + expf(-q[0]));
                float gf = 1.0f / (1.0f + expf(-q[1]));
                float gg = tanhf(q[2]);
                float go = 1.0f / (1.0f + expf(-q[3]));
                float cv = gf * cst0r[b * 16 + u] + gi * gg;
                cst0r[b * 16 + u] = cv;
                float hv = go * tanhf(cv);
                int j = blk * 16 + u;
                g_hst[0][b * HID + j] = __float2half(hv);
            }
        } else {
            // layers 1,2 recurrent: N=128 tiles
            int lyr = 1 + ((blk - 64) >> 5);
            int n0  = ((blk - 64) & 31) * 128;
            #pragma unroll
            for (int nf = 0; nf < 4; nf++) wmma::fill_fragment(a4[nf], 0.0f);
            run_gemm<4>(a4, sA, sB, tid, wm, wn, g_hst[lyr], HID, g_w[lyr], HID, n0, 8);
            #pragma unroll
            for (int nf = 0; nf < 4; nf++)
                wmma::store_matrix_sync(&g_gate[lyr][(wm * 16) * G4 + n0 + wn * 64 + nf * 16],
                                        a4[nf], G4, wmma::mem_row_major);
        }
        gbar(++gen);

        // ---- Phase B: gates1 = Wih2 x h0 + stored recurrent -> cell1 (all blocks, N=32)
        {
            int n0c = blk * 32;
            wmma::fill_fragment(a1[0], 0.0f);
            run_gemm<1>(a1, sA, sB, tid, wm, wn, g_hst[0], HID, g_w[3], HID, n0c, 8);
            wmma::store_matrix_sync(&cs[(wm * 16) * 64 + wn * 16], a1[0], 64, wmma::mem_row_major);
            __syncthreads();
            const float* bias = g_bias[1];
            for (int p = tid; p < 512; p += 256) {
                int b = p >> 3, u = p & 7;
                float q[4];
                #pragma unroll
                for (int m = 0; m < 4; m++) {
                    int cl = 4 * u + m;
                    q[m] = cs[b * 64 + cl] + g_gate[1][b * G4 + n0c + cl] + bias[n0c + cl];
                }
                float gi = 1.0f / (1.0f + expf(-q[0]));
                float gf = 1.0f / (1.0f + expf(-q[1]));
                float gg = tanhf(q[2]);
                float go = 1.0f / (1.0f + expf(-q[3]));
                float cv = gf * cst1[b * 8 + u] + gi * gg;
                cst1[b * 8 + u] = cv;
                float hv = go * tanhf(cv);
                int j = (n0c >> 2) + u;
                g_hst[1][b * HID + j] = __float2half(hv);
            }
        }
        gbar(++gen);

        // ---- Phase C: gates2 = Wih3 x h1 + stored recurrent -> cell2, save h2
        {
            int n0c = blk * 32;
            wmma::fill_fragment(a1[0], 0.0f);
            run_gemm<1>(a1, sA, sB, tid, wm, wn, g_hst[1], HID, g_w[4], HID, n0c, 8);
            wmma::store_matrix_sync(&cs[(wm * 16) * 64 + wn * 16], a1[0], 64, wmma::mem_row_major);
            __syncthreads();
            const float* bias = g_bias[2];
            for (int p = tid; p < 512; p += 256) {
                int b = p >> 3, u = p & 7;
                float q[4];
                #pragma unroll
                for (int m = 0; m < 4; m++) {
                    int cl = 4 * u + m;
                    q[m] = cs[b * 64 + cl] + g_gate[2][b * G4 + n0c + cl] + bias[n0c + cl];
                }
                float gi = 1.0f / (1.0f + expf(-q[0]));
                float gf = 1.0f / (1.0f + expf(-q[1]));
                float gg = tanhf(q[2]);
                float go = 1.0f / (1.0f + expf(-q[3]));
                float cv = gf * cst2[b * 8 + u] + gi * gg;
                cst2[b * 8 + u] = cv;
                float hv = go * tanhf(cv);
                int j = (n0c >> 2) + u;
                h16 hh = __float2half(hv);
                g_hst[2][b * HID + j] = hh;
                g_h2all[(long)t * BAT * HID + b * HID + j] = hh;
            }
        }
        gbar(++gen);
    }
}

// ---------------- final decoder: out[b][t][o] = h2all[t] x dec^T + db ----------------
__global__ __launch_bounds__(256) void dec_final(float* __restrict__ out) {
    extern __shared__ char sraw[];
    h16* sA = (h16*)sraw;
    h16* sB = sA + 3 * 64 * SMK;
    float* cs = (float*)((char*)(sB + 3 * 128 * SMK));   // [64][96]

    int tid = threadIdx.x, warp = tid >> 5, wm = warp & 3, wn = warp >> 2;
    int t  = blockIdx.x;
    int n0 = blockIdx.y * 96;

    wmma::fragment<wmma::accumulator, 16, 16, 16, float> a3[3];
    #pragma unroll
    for (int nf = 0; nf < 3; nf++) wmma::fill_fragment(a3[nf], 0.0f);
    run_gemm<3>(a3, sA, sB, tid, wm, wn,
                g_h2all + (long)t * BAT * HID, HID, g_dec, HID, n0, 8);
    #pragma unroll
    for (int nf = 0; nf < 3; nf++)
        wmma::store_matrix_sync(&cs[(wm * 16) * 96 + wn * 48 + nf * 16],
                                a3[nf], 96, wmma::mem_row_major);
    __syncthreads();
    for (int p = tid; p < 64 * 96; p += 256) {
        int b = p / 96, u = p % 96;
        int col = n0 + u;
        if (col < INS)
            out[b * (TT * INS) + t * INS + col] = cs[b * 96 + u] + g_dbias[col];
    }
}

// ---------------- launch ----------------
extern "C" void kernel_launch(void* const* d_in, const int* in_sizes, int n_in,
                              void* d_out, int out_size) {
    const float* rs    = (const float*)d_in[0];
    const float* wih1  = (const float*)d_in[1];
    const float* whh1  = (const float*)d_in[2];
    const float* bih1  = (const float*)d_in[3];
    const float* bhh1  = (const float*)d_in[4];
    const float* wih2  = (const float*)d_in[5];
    const float* whh2  = (const float*)d_in[6];
    const float* bih2  = (const float*)d_in[7];
    const float* bhh2  = (const float*)d_in[8];
    const float* wih3  = (const float*)d_in[9];
    const float* whh3  = (const float*)d_in[10];
    const float* bih3  = (const float*)d_in[11];
    const float* bhh3  = (const float*)d_in[12];
    const float* decw  = (const float*)d_in[13];
    const float* decb  = (const float*)d_in[14];
    float* out = (float*)d_out;

    cudaFuncSetAttribute(persist,   cudaFuncAttributeMaxDynamicSharedMemorySize, SMEM_BYTES);
    cudaFuncSetAttribute(dec_final, cudaFuncAttributeMaxDynamicSharedMemorySize, SMEM_BYTES);
    cudaFuncSetAttribute(prep_gx,   cudaFuncAttributeMaxDynamicSharedMemorySize, PREP_SMEM);
    cudaFuncSetAttribute(prep_wf,   cudaFuncAttributeMaxDynamicSharedMemorySize, PREP_SMEM);

    prep_wh<<<2048, 256>>>(whh1, 0);
    prep_wh<<<2048, 256>>>(whh2, 1);
    prep_wh<<<2048, 256>>>(whh3, 2);
    prep_wh<<<2048, 256>>>(wih2, 3);
    prep_wh<<<2048, 256>>>(wih3, 4);
    prep_wx0<<<512, 256>>>(wih1);
    prep_dec<<<256, 256>>>(decw);
    prep_bias<<<16, 256>>>(bih1, bhh1, 0);
    prep_bias<<<16, 256>>>(bih2, bhh2, 1);
    prep_bias<<<16, 256>>>(bih3, bhh3, 2);
    prep_wxdb<<<16, 256>>>(wih1, decb);
    prep_dbias<<<1, 256>>>(decb);
    prep_frames<<<1024, 256>>>(rs);
    prep_zero<<<512, 256>>>();

    dim3 wfg(64, 8);
    prep_wf<<<wfg, 256, PREP_SMEM>>>();
    prep_wfcvt<<<1024, 256>>>();
    dim3 gxg(32, NCOND);
    prep_gx<<<gxg, 256, PREP_SMEM>>>();

    persist<<<NB, 256, SMEM_BYTES>>>();
    dim3 dg(TT, 2);
    dec_final<<<dg, 256, SMEM_BYTES>>>(out);
}